// round 16
// baseline (speedup 1.0000x reference)
#include <cuda_runtime.h>
#include <cuda_fp16.h>

#define DIM 512
#define NHEAD 16
#define HDIM 32
#define NB 1024
#define NTOK 49
#define MROWS (NB * NTOK)   // 50176
#define QSCALE 0.17677669529663687f  // 32^-0.5

// ---------------- scratch (__device__ globals; no allocs allowed) ----------
__device__ __half g_Q[(size_t)MROWS * DIM];
__device__ __half g_K[(size_t)MROWS * DIM];
__device__ __half g_V[(size_t)MROWS * DIM];
__device__ __half g_G[(size_t)MROWS * DIM];
__device__ __half g_X16[3][(size_t)MROWS * DIM];   // fp16(x), fp16(x2), fp16(x3)
__device__ __half g_O16[(size_t)MROWS * DIM];      // fp16 attention output
// weight slots (K-major [N][K], fp16): 0:K 1:G 2:Q 3:V 4:proj
//   (K|G contiguous and Q|V contiguous -> two fused projection launches)
__device__ __half g_W[5][DIM * DIM];

// ---------------- helpers --------------------------------------------------
__device__ __forceinline__ unsigned smem_u32(const void* p) {
    unsigned a;
    asm("{ .reg .u64 t; cvta.to.shared.u64 t, %1; cvt.u32.u64 %0, t; }" : "=r"(a) : "l"(p));
    return a;
}
__device__ __forceinline__ unsigned pack_h2(__half a, __half b) {
    return (unsigned)__half_as_ushort(a) | ((unsigned)__half_as_ushort(b) << 16);
}
__device__ __forceinline__ void ldsm4(unsigned* r, unsigned addr) {
    asm volatile("ldmatrix.sync.aligned.m8n8.x4.shared.b16 {%0,%1,%2,%3}, [%4];"
        : "=r"(r[0]), "=r"(r[1]), "=r"(r[2]), "=r"(r[3]) : "r"(addr));
}
__device__ __forceinline__ void mma16816(float* d, const unsigned* a, unsigned b0, unsigned b1) {
    asm volatile("mma.sync.aligned.m16n8k16.row.col.f32.f16.f16.f32 "
        "{%0,%1,%2,%3}, {%4,%5,%6,%7}, {%8,%9}, {%0,%1,%2,%3};"
        : "+f"(d[0]), "+f"(d[1]), "+f"(d[2]), "+f"(d[3])
        : "r"(a[0]), "r"(a[1]), "r"(a[2]), "r"(a[3]), "r"(b0), "r"(b1));
}
__device__ __forceinline__ void cpa16(unsigned saddr, const void* g) {
    asm volatile("cp.async.cg.shared.global [%0], [%1], 16;" :: "r"(saddr), "l"(g));
}
#define CP_COMMIT() asm volatile("cp.async.commit_group;" ::: "memory")
#define CP_WAIT0()  asm volatile("cp.async.wait_group 0;" ::: "memory")

// ---------------------------------------------------------------------------
// Input round: fp32 -> fp16 for x / x2 / x3 (one launch, grid.y selects input)
// ---------------------------------------------------------------------------
__global__ void __launch_bounds__(256)
fsplit(const float* __restrict__ X0, const float* __restrict__ X1,
       const float* __restrict__ X2, __half* __restrict__ Out, size_t plane, int n4) {
    int i = blockIdx.x * 256 + threadIdx.x;
    if (i >= n4) return;
    const float* X = (blockIdx.y == 0) ? X0 : (blockIdx.y == 1) ? X1 : X2;
    float4 v = ((const float4*)X)[i];
    uint2 p;
    p.x = pack_h2(__float2half_rn(v.x), __float2half_rn(v.y));
    p.y = pack_h2(__float2half_rn(v.z), __float2half_rn(v.w));
    ((uint2*)(Out + blockIdx.y * plane))[i] = p;
}

// ---------------------------------------------------------------------------
// Weight transpose + fp16 round: T[n*512+k] = fp16(W[k*ldb + n])
// ---------------------------------------------------------------------------
__global__ void tsplit(const float* __restrict__ W, int ldb,
                       __half* __restrict__ Th) {
    __shared__ float t[32][33];
    int k0 = blockIdx.x * 32, n0 = blockIdx.y * 32;
    int tx = threadIdx.x, ty = threadIdx.y;
#pragma unroll
    for (int j = 0; j < 32; j += 8)
        t[ty + j][tx] = W[(size_t)(k0 + ty + j) * ldb + n0 + tx];
    __syncthreads();
#pragma unroll
    for (int j = 0; j < 32; j += 8) {
        float v = t[tx][ty + j];
        Th[(size_t)(n0 + ty + j) * DIM + k0 + tx] = __float2half_rn(v);
    }
}

// ---------------------------------------------------------------------------
// Warp-MMA fp16 GEMM (R12-proven mainloop, single-buffered):
//   C = A @ W^T + bias.  A selected per n-band (A0 below nsplit, A1 above);
//   output fp16 (H0/H1) or fp32 (C0/C1).
//   CTA tile 128x128, K-chunk 64, 8 warps (warp tile 64x32).
// ---------------------------------------------------------------------------
#define OFF_AH 0
#define OFF_BH 16384
#define GEMM_SMEM 32768

__global__ void __launch_bounds__(256, 2)
gemm_tc(const __half* __restrict__ A0, const __half* __restrict__ A1,
        const __half* __restrict__ Bh,
        const float* __restrict__ bias0, const float* __restrict__ bias1,
        float* __restrict__ C0, float* __restrict__ C1,
        __half* __restrict__ H0, __half* __restrict__ H1, int nsplit) {
    extern __shared__ char smem[];
    const unsigned sb = smem_u32(smem);
    const int tid = threadIdx.x, wid = tid >> 5, lane = tid & 31;
    const int n0 = blockIdx.x * 128, m0 = blockIdx.y * 128;

    const __half* A16 = (n0 < nsplit) ? A0 : A1;
    const float* bias = (n0 < nsplit) ? bias0 : bias1;
    float* C = (n0 < nsplit) ? C0 : C1;
    __half* H = (n0 < nsplit) ? H0 : H1;
    const int nc0 = (n0 < nsplit) ? n0 : n0 - nsplit;

    const int wm = (wid >> 2) * 64;     // warp M offset (0 or 64)
    const int wn = (wid & 3) * 32;      // warp N offset (0,32,64,96)

    // ldmatrix per-lane geometry
    const int grp = lane >> 3, lr = lane & 7;
    const int rA = wm + lr + ((grp & 1) << 3);
    const int rB = wn + lr + ((grp & 1) << 3);
    const int cadd = (grp >> 1) & 1;
    const int amod = rA & 7;
    const int bmod = rB & 7;

    float acc[4][4][4];
#pragma unroll
    for (int t = 0; t < 4; t++)
#pragma unroll
        for (int u = 0; u < 4; u++)
#pragma unroll
            for (int i = 0; i < 4; i++) acc[t][u][i] = 0.f;

    for (int c = 0; c < 8; ++c) {
        const int k0 = c * 64;
        // ---- A and B fill: pure cp.async (4+4 per thread) ----
#pragma unroll
        for (int g = tid; g < 1024; g += 256) {
            int row = g >> 3, seg = g & 7;
            unsigned off = row * 128 + seg * 16;
            unsigned sw = off ^ ((off >> 3) & 0x70);
            cpa16(sb + OFF_AH + sw, A16 + (size_t)(m0 + row) * DIM + k0 + seg * 8);
            cpa16(sb + OFF_BH + sw, Bh  + (size_t)(n0 + row) * DIM + k0 + seg * 8);
        }
        CP_COMMIT();
        CP_WAIT0();
        __syncthreads();

        // ---- MMA: single pass A*B ----
#pragma unroll
        for (int ks = 0; ks < 4; ++ks) {
            const int chk = ks * 2 + cadd;
            const unsigned aoff = (unsigned)(rA * 128) + (((unsigned)(chk ^ amod)) << 4);
            const unsigned boff = (unsigned)(rB * 128) + (((unsigned)(chk ^ bmod)) << 4);
            unsigned af[4][4], bh0[4], bh1[4];
            ldsm4(bh0, sb + OFF_BH + boff);
            ldsm4(bh1, sb + OFF_BH + boff + 16 * 128);
#pragma unroll
            for (int t = 0; t < 4; ++t)
                ldsm4(af[t], sb + OFF_AH + aoff + t * 16 * 128);
#pragma unroll
            for (int t = 0; t < 4; ++t) {
                mma16816(acc[t][0], af[t], bh0[0], bh0[2]);
                mma16816(acc[t][1], af[t], bh0[1], bh0[3]);
                mma16816(acc[t][2], af[t], bh1[0], bh1[2]);
                mma16816(acc[t][3], af[t], bh1[1], bh1[3]);
            }
        }
        __syncthreads();
    }

    // ---- epilogue: bias + store (fp16 when H set, else fp32) ----
#pragma unroll
    for (int u = 0; u < 4; ++u) {
        const int col = nc0 + wn + u * 8 + (lane & 3) * 2;
        const float bx = bias[col], by = bias[col + 1];
#pragma unroll
        for (int t = 0; t < 4; ++t) {
            const int row = m0 + wm + t * 16 + (lane >> 2);
            float o00 = acc[t][u][0] + bx, o01 = acc[t][u][1] + by;
            float o10 = acc[t][u][2] + bx, o11 = acc[t][u][3] + by;
            if (H) {
                *(unsigned*)(H + (size_t)row * DIM + col) =
                    pack_h2(__float2half_rn(o00), __float2half_rn(o01));
                *(unsigned*)(H + (size_t)(row + 8) * DIM + col) =
                    pack_h2(__float2half_rn(o10), __float2half_rn(o11));
            } else {
                float2 a0 = { o00, o01 }, a1 = { o10, o11 };
                *(float2*)(C + (size_t)row * DIM + col) = a0;
                *(float2*)(C + (size_t)(row + 8) * DIM + col) = a1;
            }
        }
    }
}

// ---------------------------------------------------------------------------
// Fused attention per (b, h), warp-per-row, register-resident softmax:
//   warp owns row n; lane holds scores for cols lane / lane+32 and output
//   dim lane. Broadcast smem reads + shfl; ONE __syncthreads total.
//   FP order identical to R14 -> bit-identical output.
// ---------------------------------------------------------------------------
__global__ __launch_bounds__(256)
void attn_kernel(const __half* __restrict__ Q1, const __half* __restrict__ G,
                 const __half* __restrict__ Km, const __half* __restrict__ Vm,
                 const float* __restrict__ a_ptr, __half* __restrict__ O16) {
    __shared__ float qs[NTOK][HDIM + 1];
    __shared__ float ks[NTOK][HDIM + 1];
    __shared__ float vs[NTOK][HDIM + 1];

    const int bh = blockIdx.x;
    const int b = bh >> 4;
    const int h = bh & 15;
    const int tid = threadIdx.x;
    const float a = *a_ptr;

    const size_t base = (size_t)b * NTOK * DIM + h * HDIM;

    // half2 loads: 784 pairs cover 49x32
    for (int i = tid; i < NTOK * HDIM / 2; i += 256) {
        int n = i >> 4, d2 = i & 15;
        size_t idx = base + (size_t)n * DIM + d2 * 2;
        float2 q = __half22float2(*(const __half2*)(Q1 + idx));
        float2 g = __half22float2(*(const __half2*)(G + idx));
        float2 k = __half22float2(*(const __half2*)(Km + idx));
        float2 v = __half22float2(*(const __half2*)(Vm + idx));
        qs[n][d2 * 2]     = q.x * QSCALE * g.x;
        qs[n][d2 * 2 + 1] = q.y * QSCALE * g.y;
        ks[n][d2 * 2]     = k.x;
        ks[n][d2 * 2 + 1] = k.y;
        vs[n][d2 * 2]     = v.x;
        vs[n][d2 * 2 + 1] = v.y;
    }
    __syncthreads();

    const int warp = tid >> 5, lane = tid & 31;
    const bool has2 = (lane + 32) < NTOK;          // lanes 0..16
    const int m2 = has2 ? lane + 32 : lane;        // safe index

    for (int n = warp; n < NTOK; n += 8) {
        // scores for columns lane and lane+32 (qs read is a broadcast)
        float s1 = 0.f, s2 = 0.f;
#pragma unroll
        for (int d = 0; d < HDIM; d++) {
            float qv = qs[n][d];
            s1 = fmaf(qv, ks[lane][d], s1);
            s2 = fmaf(qv, ks[m2][d], s2);
        }
        if (!has2) s2 = -1e30f;

        float mx = fmaxf(s1, s2);
#pragma unroll
        for (int off = 16; off; off >>= 1)
            mx = fmaxf(mx, __shfl_xor_sync(0xffffffffu, mx, off));
        float e1 = __expf(s1 - mx);
        float e2 = has2 ? __expf(s2 - mx) : 0.f;
        float sum = e1 + e2;
#pragma unroll
        for (int off = 16; off; off >>= 1)
            sum += __shfl_xor_sync(0xffffffffu, sum, off);
        float inv = 1.f / sum;
        float p1 = e1 * inv, p2 = e2 * inv;

        // PV: lane owns output dim d = lane; P broadcast via shfl
        float o = vs[n][lane] * a;
#pragma unroll
        for (int m = 0; m < NTOK; m++) {
            float pm = (m < 32) ? __shfl_sync(0xffffffffu, p1, m)
                                : __shfl_sync(0xffffffffu, p2, m - 32);
            o = fmaf(pm, vs[m][lane], o);
        }
        O16[base + (size_t)n * DIM + lane] = __float2half_rn(o);
    }
}

// ---------------------------------------------------------------------------
extern "C" void kernel_launch(void* const* d_in, const int* in_sizes, int n_in,
                              void* d_out, int out_size) {
    const float* x     = (const float*)d_in[0];
    const float* x2    = (const float*)d_in[1];
    const float* x3    = (const float*)d_in[2];
    const float* Wqkv  = (const float*)d_in[3];
    const float* bqkv  = (const float*)d_in[4];
    const float* Wqkv2 = (const float*)d_in[5];
    const float* bqkv2 = (const float*)d_in[6];
    const float* Wgw   = (const float*)d_in[7];
    const float* bgw   = (const float*)d_in[8];
    const float* Wproj = (const float*)d_in[9];
    const float* bproj = (const float*)d_in[10];
    const float* a     = (const float*)d_in[11];
    float* out = (float*)d_out;

    __half *Q, *K, *V, *G, *X16, *O16, *W;
    cudaGetSymbolAddress((void**)&Q, g_Q);
    cudaGetSymbolAddress((void**)&K, g_K);
    cudaGetSymbolAddress((void**)&V, g_V);
    cudaGetSymbolAddress((void**)&G, g_G);
    cudaGetSymbolAddress((void**)&X16, g_X16);
    cudaGetSymbolAddress((void**)&O16, g_O16);
    cudaGetSymbolAddress((void**)&W, g_W);

    const size_t PL = (size_t)MROWS * DIM;
    const size_t WS = (size_t)DIM * DIM;
    cudaFuncSetAttribute(gemm_tc, cudaFuncAttributeMaxDynamicSharedMemorySize, GEMM_SMEM);

    // Round inputs to fp16 (one launch for x, x2, x3)
    const int n4 = (int)(PL / 4);
    dim3 fg((n4 + 255) / 256, 3);
    fsplit<<<fg, 256>>>(x, x2, x3, X16, PL, n4);

    dim3 tsG(16, 16), tsB(32, 8);
    // slots: 0:K (Wqkv cols [512,1024)); 1:G (Wgw); 2:Q (Wqkv2 [0,512));
    //        3:V (Wqkv2 [1024,1536)); 4:proj (Wproj)
    tsplit<<<tsG, tsB>>>(Wqkv  + DIM,     3 * DIM, W + 0 * WS);
    tsplit<<<tsG, tsB>>>(Wgw,             DIM,     W + 1 * WS);
    tsplit<<<tsG, tsB>>>(Wqkv2,           3 * DIM, W + 2 * WS);
    tsplit<<<tsG, tsB>>>(Wqkv2 + 2 * DIM, 3 * DIM, W + 3 * WS);
    tsplit<<<tsG, tsB>>>(Wproj,           DIM,     W + 4 * WS);

    const int BIG = 1 << 30;
    dim3 gkg(8, MROWS / 128);   // fused K|G (bands 0-3: K from x; 4-7: G from x2)
    dim3 gqv(8, MROWS / 128);   // fused Q|V (A = x3 for both)
    dim3 gp(4, MROWS / 128);    // proj

    // K and Gate projections fused -> fp16 K, G
    gemm_tc<<<gkg, 256, GEMM_SMEM>>>(X16 + 0 * PL, X16 + 1 * PL, W + 0 * WS,
                                     bqkv + DIM, bgw, nullptr, nullptr,
                                     K, G, DIM);
    // Q and V projections fused -> fp16 Q, V
    gemm_tc<<<gqv, 256, GEMM_SMEM>>>(X16 + 2 * PL, X16 + 2 * PL, W + 2 * WS,
                                     bqkv2, bqkv2 + 2 * DIM, nullptr, nullptr,
                                     Q, V, DIM);

    attn_kernel<<<NB * NHEAD, 256>>>(Q, G, K, V, a, O16);

    // Output projection (A = fp16 attention output) -> fp32 out
    gemm_tc<<<gp, 256, GEMM_SMEM>>>(O16, O16, W + 4 * WS,
                                    bproj, nullptr, out, nullptr,
                                    nullptr, nullptr, BIG);
}

// round 17
// speedup vs baseline: 1.4145x; 1.4145x over previous
#include <cuda_runtime.h>
#include <cuda_fp16.h>

#define DIM 512
#define NHEAD 16
#define HDIM 32
#define NB 1024
#define NTOK 49
#define MROWS (NB * NTOK)   // 50176
#define QSCALE 0.17677669529663687f  // 32^-0.5

// ---------------- scratch (__device__ globals; no allocs allowed) ----------
__device__ __half g_Q[(size_t)MROWS * DIM];
__device__ __half g_K[(size_t)MROWS * DIM];
__device__ __half g_V[(size_t)MROWS * DIM];
__device__ __half g_G[(size_t)MROWS * DIM];
__device__ __half g_X16[3][(size_t)MROWS * DIM];   // fp16(x), fp16(x2), fp16(x3)
__device__ __half g_O16[(size_t)MROWS * DIM];      // fp16 attention output
// weight slots (K-major [N][K], fp16): 0:K 1:G 2:Q 3:V 4:proj
//   (K|G contiguous and Q|V contiguous -> two fused projection launches)
__device__ __half g_W[5][DIM * DIM];

// ---------------- helpers --------------------------------------------------
__device__ __forceinline__ unsigned smem_u32(const void* p) {
    unsigned a;
    asm("{ .reg .u64 t; cvta.to.shared.u64 t, %1; cvt.u32.u64 %0, t; }" : "=r"(a) : "l"(p));
    return a;
}
__device__ __forceinline__ unsigned pack_h2(__half a, __half b) {
    return (unsigned)__half_as_ushort(a) | ((unsigned)__half_as_ushort(b) << 16);
}
__device__ __forceinline__ void ldsm4(unsigned* r, unsigned addr) {
    asm volatile("ldmatrix.sync.aligned.m8n8.x4.shared.b16 {%0,%1,%2,%3}, [%4];"
        : "=r"(r[0]), "=r"(r[1]), "=r"(r[2]), "=r"(r[3]) : "r"(addr));
}
__device__ __forceinline__ void mma16816(float* d, const unsigned* a, unsigned b0, unsigned b1) {
    asm volatile("mma.sync.aligned.m16n8k16.row.col.f32.f16.f16.f32 "
        "{%0,%1,%2,%3}, {%4,%5,%6,%7}, {%8,%9}, {%0,%1,%2,%3};"
        : "+f"(d[0]), "+f"(d[1]), "+f"(d[2]), "+f"(d[3])
        : "r"(a[0]), "r"(a[1]), "r"(a[2]), "r"(a[3]), "r"(b0), "r"(b1));
}
__device__ __forceinline__ void cpa16(unsigned saddr, const void* g) {
    asm volatile("cp.async.cg.shared.global [%0], [%1], 16;" :: "r"(saddr), "l"(g));
}
#define CP_COMMIT() asm volatile("cp.async.commit_group;" ::: "memory")
#define CP_WAIT0()  asm volatile("cp.async.wait_group 0;" ::: "memory")

// ---------------------------------------------------------------------------
// Input round: fp32 -> fp16 for x / x2 / x3 (one launch, grid.y selects input)
// ---------------------------------------------------------------------------
__global__ void __launch_bounds__(256)
fsplit(const float* __restrict__ X0, const float* __restrict__ X1,
       const float* __restrict__ X2, __half* __restrict__ Out, size_t plane, int n4) {
    int i = blockIdx.x * 256 + threadIdx.x;
    if (i >= n4) return;
    const float* X = (blockIdx.y == 0) ? X0 : (blockIdx.y == 1) ? X1 : X2;
    float4 v = ((const float4*)X)[i];
    uint2 p;
    p.x = pack_h2(__float2half_rn(v.x), __float2half_rn(v.y));
    p.y = pack_h2(__float2half_rn(v.z), __float2half_rn(v.w));
    ((uint2*)(Out + blockIdx.y * plane))[i] = p;
}

// ---------------------------------------------------------------------------
// Weight transpose + fp16 round: T[n*512+k] = fp16(W[k*ldb + n])
// ---------------------------------------------------------------------------
__global__ void tsplit(const float* __restrict__ W, int ldb,
                       __half* __restrict__ Th) {
    __shared__ float t[32][33];
    int k0 = blockIdx.x * 32, n0 = blockIdx.y * 32;
    int tx = threadIdx.x, ty = threadIdx.y;
#pragma unroll
    for (int j = 0; j < 32; j += 8)
        t[ty + j][tx] = W[(size_t)(k0 + ty + j) * ldb + n0 + tx];
    __syncthreads();
#pragma unroll
    for (int j = 0; j < 32; j += 8) {
        float v = t[tx][ty + j];
        Th[(size_t)(n0 + ty + j) * DIM + k0 + tx] = __float2half_rn(v);
    }
}

// ---------------------------------------------------------------------------
// Warp-MMA fp16 GEMM (R12-proven mainloop, single-buffered):
//   C = A @ W^T + bias.  A selected per n-band (A0 below nsplit, A1 above);
//   output fp16 (H0/H1) or fp32 (C0/C1).
//   CTA tile 128x128, K-chunk 64, 8 warps (warp tile 64x32).
// ---------------------------------------------------------------------------
#define OFF_AH 0
#define OFF_BH 16384
#define GEMM_SMEM 32768

__global__ void __launch_bounds__(256, 2)
gemm_tc(const __half* __restrict__ A0, const __half* __restrict__ A1,
        const __half* __restrict__ Bh,
        const float* __restrict__ bias0, const float* __restrict__ bias1,
        float* __restrict__ C0, float* __restrict__ C1,
        __half* __restrict__ H0, __half* __restrict__ H1, int nsplit) {
    extern __shared__ char smem[];
    const unsigned sb = smem_u32(smem);
    const int tid = threadIdx.x, wid = tid >> 5, lane = tid & 31;
    const int n0 = blockIdx.x * 128, m0 = blockIdx.y * 128;

    const __half* A16 = (n0 < nsplit) ? A0 : A1;
    const float* bias = (n0 < nsplit) ? bias0 : bias1;
    float* C = (n0 < nsplit) ? C0 : C1;
    __half* H = (n0 < nsplit) ? H0 : H1;
    const int nc0 = (n0 < nsplit) ? n0 : n0 - nsplit;

    const int wm = (wid >> 2) * 64;     // warp M offset (0 or 64)
    const int wn = (wid & 3) * 32;      // warp N offset (0,32,64,96)

    // ldmatrix per-lane geometry
    const int grp = lane >> 3, lr = lane & 7;
    const int rA = wm + lr + ((grp & 1) << 3);
    const int rB = wn + lr + ((grp & 1) << 3);
    const int cadd = (grp >> 1) & 1;
    const int amod = rA & 7;
    const int bmod = rB & 7;

    float acc[4][4][4];
#pragma unroll
    for (int t = 0; t < 4; t++)
#pragma unroll
        for (int u = 0; u < 4; u++)
#pragma unroll
            for (int i = 0; i < 4; i++) acc[t][u][i] = 0.f;

    for (int c = 0; c < 8; ++c) {
        const int k0 = c * 64;
        // ---- A and B fill: pure cp.async (4+4 per thread) ----
#pragma unroll
        for (int g = tid; g < 1024; g += 256) {
            int row = g >> 3, seg = g & 7;
            unsigned off = row * 128 + seg * 16;
            unsigned sw = off ^ ((off >> 3) & 0x70);
            cpa16(sb + OFF_AH + sw, A16 + (size_t)(m0 + row) * DIM + k0 + seg * 8);
            cpa16(sb + OFF_BH + sw, Bh  + (size_t)(n0 + row) * DIM + k0 + seg * 8);
        }
        CP_COMMIT();
        CP_WAIT0();
        __syncthreads();

        // ---- MMA: single pass A*B ----
#pragma unroll
        for (int ks = 0; ks < 4; ++ks) {
            const int chk = ks * 2 + cadd;
            const unsigned aoff = (unsigned)(rA * 128) + (((unsigned)(chk ^ amod)) << 4);
            const unsigned boff = (unsigned)(rB * 128) + (((unsigned)(chk ^ bmod)) << 4);
            unsigned af[4][4], bh0[4], bh1[4];
            ldsm4(bh0, sb + OFF_BH + boff);
            ldsm4(bh1, sb + OFF_BH + boff + 16 * 128);
#pragma unroll
            for (int t = 0; t < 4; ++t)
                ldsm4(af[t], sb + OFF_AH + aoff + t * 16 * 128);
#pragma unroll
            for (int t = 0; t < 4; ++t) {
                mma16816(acc[t][0], af[t], bh0[0], bh0[2]);
                mma16816(acc[t][1], af[t], bh0[1], bh0[3]);
                mma16816(acc[t][2], af[t], bh1[0], bh1[2]);
                mma16816(acc[t][3], af[t], bh1[1], bh1[3]);
            }
        }
        __syncthreads();
    }

    // ---- epilogue: bias + store (fp16 when H set, else fp32) ----
#pragma unroll
    for (int u = 0; u < 4; ++u) {
        const int col = nc0 + wn + u * 8 + (lane & 3) * 2;
        const float bx = bias[col], by = bias[col + 1];
#pragma unroll
        for (int t = 0; t < 4; ++t) {
            const int row = m0 + wm + t * 16 + (lane >> 2);
            float o00 = acc[t][u][0] + bx, o01 = acc[t][u][1] + by;
            float o10 = acc[t][u][2] + bx, o11 = acc[t][u][3] + by;
            if (H) {
                *(unsigned*)(H + (size_t)row * DIM + col) =
                    pack_h2(__float2half_rn(o00), __float2half_rn(o01));
                *(unsigned*)(H + (size_t)(row + 8) * DIM + col) =
                    pack_h2(__float2half_rn(o10), __float2half_rn(o11));
            } else {
                float2 a0 = { o00, o01 }, a1 = { o10, o11 };
                *(float2*)(C + (size_t)row * DIM + col) = a0;
                *(float2*)(C + (size_t)(row + 8) * DIM + col) = a1;
            }
        }
    }
}

// ---------------------------------------------------------------------------
// Fused attention per (b, h) — R14-proven version (fp16 in, fp32 compute,
// fp16 out; S staged in smem, three barriers).
// ---------------------------------------------------------------------------
__global__ __launch_bounds__(256)
void attn_kernel(const __half* __restrict__ Q1, const __half* __restrict__ G,
                 const __half* __restrict__ Km, const __half* __restrict__ Vm,
                 const float* __restrict__ a_ptr, __half* __restrict__ O16) {
    __shared__ float qs[NTOK][HDIM + 1];
    __shared__ float ks[NTOK][HDIM + 1];
    __shared__ float vs[NTOK][HDIM + 1];
    __shared__ float S[NTOK][NTOK + 1];

    const int bh = blockIdx.x;
    const int b = bh >> 4;
    const int h = bh & 15;
    const int tid = threadIdx.x;
    const float a = *a_ptr;

    const size_t base = (size_t)b * NTOK * DIM + h * HDIM;

    // half2 loads: 784 pairs cover 49x32
    for (int i = tid; i < NTOK * HDIM / 2; i += 256) {
        int n = i >> 4, d2 = i & 15;
        size_t idx = base + (size_t)n * DIM + d2 * 2;
        float2 q = __half22float2(*(const __half2*)(Q1 + idx));
        float2 g = __half22float2(*(const __half2*)(G + idx));
        float2 k = __half22float2(*(const __half2*)(Km + idx));
        float2 v = __half22float2(*(const __half2*)(Vm + idx));
        qs[n][d2 * 2]     = q.x * QSCALE * g.x;
        qs[n][d2 * 2 + 1] = q.y * QSCALE * g.y;
        ks[n][d2 * 2]     = k.x;
        ks[n][d2 * 2 + 1] = k.y;
        vs[n][d2 * 2]     = v.x;
        vs[n][d2 * 2 + 1] = v.y;
    }
    __syncthreads();

    for (int i = tid; i < NTOK * NTOK; i += 256) {
        int n = i / NTOK, m = i - n * NTOK;
        float s = 0.f;
#pragma unroll
        for (int d = 0; d < HDIM; d++) s = fmaf(qs[n][d], ks[m][d], s);
        S[n][m] = s;
    }
    __syncthreads();

    const int warp = tid >> 5, lane = tid & 31;
    for (int n = warp; n < NTOK; n += 8) {
        float v1 = S[n][lane];
        float v2 = (lane + 32 < NTOK) ? S[n][lane + 32] : -1e30f;
        float mx = fmaxf(v1, v2);
#pragma unroll
        for (int off = 16; off; off >>= 1)
            mx = fmaxf(mx, __shfl_xor_sync(0xffffffffu, mx, off));
        float e1 = __expf(v1 - mx);
        float e2 = (lane + 32 < NTOK) ? __expf(v2 - mx) : 0.f;
        float sum = e1 + e2;
#pragma unroll
        for (int off = 16; off; off >>= 1)
            sum += __shfl_xor_sync(0xffffffffu, sum, off);
        float inv = 1.f / sum;
        S[n][lane] = e1 * inv;
        if (lane + 32 < NTOK) S[n][lane + 32] = e2 * inv;
    }
    __syncthreads();

    for (int i = tid; i < NTOK * HDIM; i += 256) {
        int n = i >> 5, d = i & 31;
        float o = vs[n][d] * a;
#pragma unroll
        for (int m = 0; m < NTOK; m++) o = fmaf(S[n][m], vs[m][d], o);
        O16[base + (size_t)n * DIM + d] = __float2half_rn(o);
    }
}

// ---------------------------------------------------------------------------
extern "C" void kernel_launch(void* const* d_in, const int* in_sizes, int n_in,
                              void* d_out, int out_size) {
    const float* x     = (const float*)d_in[0];
    const float* x2    = (const float*)d_in[1];
    const float* x3    = (const float*)d_in[2];
    const float* Wqkv  = (const float*)d_in[3];
    const float* bqkv  = (const float*)d_in[4];
    const float* Wqkv2 = (const float*)d_in[5];
    const float* bqkv2 = (const float*)d_in[6];
    const float* Wgw   = (const float*)d_in[7];
    const float* bgw   = (const float*)d_in[8];
    const float* Wproj = (const float*)d_in[9];
    const float* bproj = (const float*)d_in[10];
    const float* a     = (const float*)d_in[11];
    float* out = (float*)d_out;

    __half *Q, *K, *V, *G, *X16, *O16, *W;
    cudaGetSymbolAddress((void**)&Q, g_Q);
    cudaGetSymbolAddress((void**)&K, g_K);
    cudaGetSymbolAddress((void**)&V, g_V);
    cudaGetSymbolAddress((void**)&G, g_G);
    cudaGetSymbolAddress((void**)&X16, g_X16);
    cudaGetSymbolAddress((void**)&O16, g_O16);
    cudaGetSymbolAddress((void**)&W, g_W);

    const size_t PL = (size_t)MROWS * DIM;
    const size_t WS = (size_t)DIM * DIM;
    cudaFuncSetAttribute(gemm_tc, cudaFuncAttributeMaxDynamicSharedMemorySize, GEMM_SMEM);

    // Round inputs to fp16 (one launch for x, x2, x3)
    const int n4 = (int)(PL / 4);
    dim3 fg((n4 + 255) / 256, 3);
    fsplit<<<fg, 256>>>(x, x2, x3, X16, PL, n4);

    dim3 tsG(16, 16), tsB(32, 8);
    // slots: 0:K (Wqkv cols [512,1024)); 1:G (Wgw); 2:Q (Wqkv2 [0,512));
    //        3:V (Wqkv2 [1024,1536)); 4:proj (Wproj)
    tsplit<<<tsG, tsB>>>(Wqkv  + DIM,     3 * DIM, W + 0 * WS);
    tsplit<<<tsG, tsB>>>(Wgw,             DIM,     W + 1 * WS);
    tsplit<<<tsG, tsB>>>(Wqkv2,           3 * DIM, W + 2 * WS);
    tsplit<<<tsG, tsB>>>(Wqkv2 + 2 * DIM, 3 * DIM, W + 3 * WS);
    tsplit<<<tsG, tsB>>>(Wproj,           DIM,     W + 4 * WS);

    const int BIG = 1 << 30;
    dim3 gkg(8, MROWS / 128);   // fused K|G (bands 0-3: K from x; 4-7: G from x2)
    dim3 gqv(8, MROWS / 128);   // fused Q|V (A = x3 for both)
    dim3 gp(4, MROWS / 128);    // proj

    // K and Gate projections fused -> fp16 K, G
    gemm_tc<<<gkg, 256, GEMM_SMEM>>>(X16 + 0 * PL, X16 + 1 * PL, W + 0 * WS,
                                     bqkv + DIM, bgw, nullptr, nullptr,
                                     K, G, DIM);
    // Q and V projections fused -> fp16 Q, V
    gemm_tc<<<gqv, 256, GEMM_SMEM>>>(X16 + 2 * PL, X16 + 2 * PL, W + 2 * WS,
                                     bqkv2, bqkv2 + 2 * DIM, nullptr, nullptr,
                                     Q, V, DIM);

    attn_kernel<<<NB * NHEAD, 256>>>(Q, G, K, V, a, O16);

    // Output projection (A = fp16 attention output) -> fp32 out
    gemm_tc<<<gp, 256, GEMM_SMEM>>>(O16, O16, W + 4 * WS,
                                    bproj, nullptr, out, nullptr,
                                    nullptr, nullptr, BIG);
}